// round 2
// baseline (speedup 1.0000x reference)
#include <cuda_runtime.h>
#include <cstdint>
#include <cstddef>

#define N_NODES   50000
#define N_EDGES   600000
#define DIM       128
#define NUM_GRAPHS 64
#define TB 256

// ---------------- scratch (device globals; re-initialized every launch) ----------------
__device__ float g_dis4[4][N_NODES];              // per-channel D^-1/2 (deg accumulated in place)
__device__ float g_disu[N_NODES];                 // unweighted D^-1/2
__device__ float g_agg1[4][N_NODES][DIM];         // layer-1 aggregated x, per channel
__device__ float g_H   [N_NODES][4 * DIM];        // concat(relu(conv1A..D))
__device__ float g_Z2  [N_NODES][2 * DIM];        // H @ W2
__device__ float g_agg2[N_NODES][2 * DIM];        // aggregated Z2
__device__ float g_H2  [N_NODES][2 * DIM];        // relu(agg2 + b2)
__device__ float g_Z3  [N_NODES][DIM];            // H2 @ W3
__device__ float g_agg3[N_NODES][DIM];            // aggregated Z3 (bias b3 added at pooling)
__device__ float g_sums[NUM_GRAPHS][DIM];
__device__ float g_maxs[NUM_GRAPHS][DIM];
__device__ int   g_cnts[NUM_GRAPHS];

// ---------------- helpers ----------------
__device__ __forceinline__ void red4(float* p, float a, float b, float c, float d) {
    asm volatile("red.global.add.v4.f32 [%0], {%1,%2,%3,%4};"
                 :: "l"(p), "f"(a), "f"(b), "f"(c), "f"(d) : "memory");
}

__device__ __forceinline__ void atomicMaxF(float* addr, float v) {
    if (v >= 0.0f) atomicMax(reinterpret_cast<int*>(addr), __float_as_int(v));
    else           atomicMin(reinterpret_cast<unsigned int*>(addr), __float_as_uint(v));
}

// ---------------- degree / normalization ----------------
__global__ void k_deg_init() {
    int v = blockIdx.x * blockDim.x + threadIdx.x;
    if (v < N_NODES) {
        g_dis4[0][v] = 1.f; g_dis4[1][v] = 1.f; g_dis4[2][v] = 1.f; g_dis4[3][v] = 1.f;
        g_disu[v] = 1.f;
    }
}

__global__ void k_deg_acc(const int* __restrict__ ei, const float* __restrict__ ea) {
    int e = blockIdx.x * blockDim.x + threadIdx.x;
    if (e >= N_EDGES) return;
    int d = ei[N_EDGES + e];
    float4 w = *reinterpret_cast<const float4*>(ea + 4 * (size_t)e);
    atomicAdd(&g_dis4[0][d], w.x);
    atomicAdd(&g_dis4[1][d], w.y);
    atomicAdd(&g_dis4[2][d], w.z);
    atomicAdd(&g_dis4[3][d], w.w);
    atomicAdd(&g_disu[d], 1.0f);
}

__global__ void k_rsqrt() {
    int v = blockIdx.x * blockDim.x + threadIdx.x;
    if (v < N_NODES) {
        #pragma unroll
        for (int c = 0; c < 4; c++) g_dis4[c][v] = rsqrtf(g_dis4[c][v]);
        g_disu[v] = rsqrtf(g_disu[v]);
    }
}

// ---------------- layer 1: aggregate x (4 channels), then GEMM ----------------
__global__ void k_agg1_init(const float* __restrict__ x) {
    int idx = blockIdx.x * blockDim.x + threadIdx.x;  // v*32 + q
    if (idx >= N_NODES * 32) return;
    int v = idx >> 5, q = idx & 31;
    float4 xv = *reinterpret_cast<const float4*>(x + (size_t)v * DIM + q * 4);
    #pragma unroll
    for (int c = 0; c < 4; c++) {
        float s = g_dis4[c][v]; s = s * s;
        float4 o = make_float4(xv.x * s, xv.y * s, xv.z * s, xv.w * s);
        *reinterpret_cast<float4*>(&g_agg1[c][v][q * 4]) = o;
    }
}

__global__ void k_scatter1(const float* __restrict__ x, const int* __restrict__ ei,
                           const float* __restrict__ ea) {
    int t = blockIdx.x * blockDim.x + threadIdx.x;
    int e = t >> 5, lane = t & 31;
    if (e >= N_EDGES) return;
    int s = __ldg(ei + e), d = __ldg(ei + N_EDGES + e);
    float4 w = *reinterpret_cast<const float4*>(ea + 4 * (size_t)e);
    float c0 = g_dis4[0][s] * w.x * g_dis4[0][d];
    float c1 = g_dis4[1][s] * w.y * g_dis4[1][d];
    float c2 = g_dis4[2][s] * w.z * g_dis4[2][d];
    float c3 = g_dis4[3][s] * w.w * g_dis4[3][d];
    float4 xv = *reinterpret_cast<const float4*>(x + (size_t)s * DIM + lane * 4);
    red4(&g_agg1[0][d][lane * 4], xv.x * c0, xv.y * c0, xv.z * c0, xv.w * c0);
    red4(&g_agg1[1][d][lane * 4], xv.x * c1, xv.y * c1, xv.z * c1, xv.w * c1);
    red4(&g_agg1[2][d][lane * 4], xv.x * c2, xv.y * c2, xv.z * c2, xv.w * c2);
    red4(&g_agg1[3][d][lane * 4], xv.x * c3, xv.y * c3, xv.z * c3, xv.w * c3);
}

// ---------------- SGEMM: 128x128 tile, BK=16, 8x8 per thread, 256 threads ----------------
__device__ __forceinline__ void sgemm_body(
    const float* __restrict__ A, int lda,
    const float* __restrict__ B, int ldb,
    float* __restrict__ C, int ldc,
    const float* __restrict__ bias, bool relu,
    int M, int N, int K, int m0, int n0)
{
    __shared__ float As[16][128];
    __shared__ float Bs[16][128];
    int tid = threadIdx.x;
    int tx = tid % 16, ty = tid / 16;
    float acc[8][8];
    #pragma unroll
    for (int i = 0; i < 8; i++)
        #pragma unroll
        for (int j = 0; j < 8; j++) acc[i][j] = 0.0f;

    for (int k0 = 0; k0 < K; k0 += 16) {
        // load A tile (128 x 16) transposed into As[k][m]
        #pragma unroll
        for (int l = 0; l < 2; l++) {
            int f = tid + l * 256;           // 512 float4s
            int m = f >> 2;
            int kk = (f & 3) * 4;
            int gm = m0 + m;
            float4 v = (gm < M)
                ? *reinterpret_cast<const float4*>(&A[(size_t)gm * lda + k0 + kk])
                : make_float4(0.f, 0.f, 0.f, 0.f);
            As[kk + 0][m] = v.x; As[kk + 1][m] = v.y;
            As[kk + 2][m] = v.z; As[kk + 3][m] = v.w;
        }
        // load B tile (16 x 128)
        #pragma unroll
        for (int l = 0; l < 2; l++) {
            int f = tid + l * 256;
            int k = f >> 5;
            int n = (f & 31) * 4;
            float4 v = *reinterpret_cast<const float4*>(&B[(size_t)(k0 + k) * ldb + n0 + n]);
            *reinterpret_cast<float4*>(&Bs[k][n]) = v;
        }
        __syncthreads();
        #pragma unroll
        for (int k = 0; k < 16; k++) {
            float a[8], b[8];
            #pragma unroll
            for (int i = 0; i < 8; i++) a[i] = As[k][ty * 8 + i];
            #pragma unroll
            for (int j = 0; j < 8; j++) b[j] = Bs[k][tx * 8 + j];
            #pragma unroll
            for (int i = 0; i < 8; i++)
                #pragma unroll
                for (int j = 0; j < 8; j++) acc[i][j] += a[i] * b[j];
        }
        __syncthreads();
    }

    #pragma unroll
    for (int i = 0; i < 8; i++) {
        int gm = m0 + ty * 8 + i;
        if (gm >= M) break;
        #pragma unroll
        for (int j = 0; j < 8; j += 4) {
            int gn = n0 + tx * 8 + j;
            float4 v = make_float4(acc[i][j], acc[i][j + 1], acc[i][j + 2], acc[i][j + 3]);
            if (bias) {
                v.x += bias[gn]; v.y += bias[gn + 1]; v.z += bias[gn + 2]; v.w += bias[gn + 3];
            }
            if (relu) {
                v.x = fmaxf(v.x, 0.f); v.y = fmaxf(v.y, 0.f);
                v.z = fmaxf(v.z, 0.f); v.w = fmaxf(v.w, 0.f);
            }
            *reinterpret_cast<float4*>(&C[(size_t)gm * ldc + gn]) = v;
        }
    }
}

struct L1Args {
    const float* W[4];
    const float* b[4];
    const float* A;   // g_agg1 base
    float*       C;   // g_H base
};

// layer-1 batched GEMM: blockIdx.z = channel, epilogue bias+relu, writes strided into H
__global__ void __launch_bounds__(256) k_gemm1(L1Args args) {
    int c = blockIdx.z;
    const float* A = args.A + (size_t)c * N_NODES * DIM;
    float* C = args.C + c * DIM;
    sgemm_body(A, DIM, args.W[c], DIM, C, 4 * DIM, args.b[c], true,
               N_NODES, DIM, DIM, blockIdx.x * 128, 0);
}

__global__ void __launch_bounds__(256) k_gemm(const float* __restrict__ A, int lda,
                                              const float* __restrict__ B, int ldb,
                                              float* __restrict__ C, int ldc,
                                              int M, int N, int K) {
    sgemm_body(A, lda, B, ldb, C, ldc, nullptr, false, M, N, K,
               blockIdx.x * 128, blockIdx.y * 128);
}

// ---------------- layer 2 aggregation (256-dim) ----------------
__global__ void k_agg2_init() {
    int idx = blockIdx.x * blockDim.x + threadIdx.x;  // v*64 + q
    if (idx >= N_NODES * 64) return;
    int v = idx >> 6, q = idx & 63;
    float s = g_disu[v]; s = s * s;
    float4 z = *reinterpret_cast<const float4*>(&g_Z2[v][q * 4]);
    float4 o = make_float4(z.x * s, z.y * s, z.z * s, z.w * s);
    *reinterpret_cast<float4*>(&g_agg2[v][q * 4]) = o;
}

__global__ void k_scatter2(const int* __restrict__ ei) {
    int t = blockIdx.x * blockDim.x + threadIdx.x;
    int e = t >> 5, lane = t & 31;
    if (e >= N_EDGES) return;
    int s = __ldg(ei + e), d = __ldg(ei + N_EDGES + e);
    float coef = g_disu[s] * g_disu[d];
    #pragma unroll
    for (int h = 0; h < 2; h++) {
        int q = lane + h * 32;
        float4 z = *reinterpret_cast<const float4*>(&g_Z2[s][q * 4]);
        red4(&g_agg2[d][q * 4], z.x * coef, z.y * coef, z.z * coef, z.w * coef);
    }
}

__global__ void k_bias_relu2(const float* __restrict__ b2) {
    int idx = blockIdx.x * blockDim.x + threadIdx.x;  // v*64 + q
    if (idx >= N_NODES * 64) return;
    int v = idx >> 6, q = idx & 63;
    float4 a = *reinterpret_cast<const float4*>(&g_agg2[v][q * 4]);
    float4 b = *reinterpret_cast<const float4*>(&b2[q * 4]);
    float4 o = make_float4(fmaxf(a.x + b.x, 0.f), fmaxf(a.y + b.y, 0.f),
                           fmaxf(a.z + b.z, 0.f), fmaxf(a.w + b.w, 0.f));
    *reinterpret_cast<float4*>(&g_H2[v][q * 4]) = o;
}

// ---------------- layer 3 aggregation (128-dim) ----------------
__global__ void k_agg3_init() {
    int idx = blockIdx.x * blockDim.x + threadIdx.x;  // v*32 + q
    if (idx >= N_NODES * 32) return;
    int v = idx >> 5, q = idx & 31;
    float s = g_disu[v]; s = s * s;
    float4 z = *reinterpret_cast<const float4*>(&g_Z3[v][q * 4]);
    float4 o = make_float4(z.x * s, z.y * s, z.z * s, z.w * s);
    *reinterpret_cast<float4*>(&g_agg3[v][q * 4]) = o;
}

__global__ void k_scatter3(const int* __restrict__ ei) {
    int t = blockIdx.x * blockDim.x + threadIdx.x;
    int e = t >> 5, lane = t & 31;
    if (e >= N_EDGES) return;
    int s = __ldg(ei + e), d = __ldg(ei + N_EDGES + e);
    float coef = g_disu[s] * g_disu[d];
    float4 z = *reinterpret_cast<const float4*>(&g_Z3[s][lane * 4]);
    red4(&g_agg3[d][lane * 4], z.x * coef, z.y * coef, z.z * coef, z.w * coef);
}

// ---------------- pooling + MLP ----------------
__global__ void k_pool_init() {
    int idx = blockIdx.x * blockDim.x + threadIdx.x;
    if (idx < NUM_GRAPHS * DIM) {
        (&g_sums[0][0])[idx] = 0.0f;
        (&g_maxs[0][0])[idx] = __int_as_float(0xff800000);  // -inf
        if (idx < NUM_GRAPHS) g_cnts[idx] = 0;
    }
}

__global__ void k_pool_acc(const int* __restrict__ batch, const float* __restrict__ b3) {
    int t = blockIdx.x * blockDim.x + threadIdx.x;
    int v = t >> 5, lane = t & 31;
    if (v >= N_NODES) return;
    int g = __ldg(batch + v);
    if (lane == 0) atomicAdd(&g_cnts[g], 1);
    float4 a = *reinterpret_cast<const float4*>(&g_agg3[v][lane * 4]);
    float4 b = *reinterpret_cast<const float4*>(&b3[lane * 4]);
    a.x += b.x; a.y += b.y; a.z += b.z; a.w += b.w;  // h3 = agg3 + b3 (no relu)
    red4(&g_sums[g][lane * 4], a.x, a.y, a.z, a.w);
    atomicMaxF(&g_maxs[g][lane * 4 + 0], a.x);
    atomicMaxF(&g_maxs[g][lane * 4 + 1], a.y);
    atomicMaxF(&g_maxs[g][lane * 4 + 2], a.z);
    atomicMaxF(&g_maxs[g][lane * 4 + 3], a.w);
}

__global__ void k_mlp(const float* __restrict__ Wm1, const float* __restrict__ bm1,
                      const float* __restrict__ Wm2, const float* __restrict__ bm2,
                      float* __restrict__ out) {
    int g = blockIdx.x;
    int t = threadIdx.x;  // 256
    __shared__ float sg[2 * DIM];
    __shared__ float sh[8];
    int cnt = g_cnts[g];
    float val;
    if (t < DIM) {
        val = g_sums[g][t] / fmaxf((float)cnt, 1.0f);
    } else {
        float m = g_maxs[g][t - DIM];
        val = (cnt > 0) ? m : 0.0f;
    }
    sg[t] = val;
    __syncthreads();
    if (t < 8) {
        float h = bm1[t];
        #pragma unroll 8
        for (int j = 0; j < 2 * DIM; j++) h += sg[j] * Wm1[j * 8 + t];
        sh[t] = fmaxf(h, 0.0f);
    }
    __syncthreads();
    if (t < 2) {
        float o = bm2[t];
        #pragma unroll
        for (int k = 0; k < 8; k++) o += sh[k] * Wm2[k * 2 + t];
        out[g * 2 + t] = o;
    }
}

// ---------------- launch ----------------
extern "C" void kernel_launch(void* const* d_in, const int* in_sizes, int n_in,
                              void* d_out, int out_size) {
    const float* x     = (const float*)d_in[0];
    const int*   ei    = (const int*)d_in[1];
    const float* ea    = (const float*)d_in[2];
    const int*   batch = (const int*)d_in[3];
    const float* W1a[4] = {(const float*)d_in[4], (const float*)d_in[6],
                           (const float*)d_in[8], (const float*)d_in[10]};
    const float* b1a[4] = {(const float*)d_in[5], (const float*)d_in[7],
                           (const float*)d_in[9], (const float*)d_in[11]};
    const float* W2  = (const float*)d_in[12];
    const float* b2  = (const float*)d_in[13];
    const float* W3  = (const float*)d_in[14];
    const float* b3  = (const float*)d_in[15];
    const float* Wm1 = (const float*)d_in[16];
    const float* bm1 = (const float*)d_in[17];
    const float* Wm2 = (const float*)d_in[18];
    const float* bm2 = (const float*)d_in[19];
    float* out = (float*)d_out;

    float *pAgg1, *pH, *pZ2, *pH2, *pZ3;
    cudaGetSymbolAddress((void**)&pAgg1, g_agg1);
    cudaGetSymbolAddress((void**)&pH,    g_H);
    cudaGetSymbolAddress((void**)&pZ2,   g_Z2);
    cudaGetSymbolAddress((void**)&pH2,   g_H2);
    cudaGetSymbolAddress((void**)&pZ3,   g_Z3);

    int nodeBlocks  = (N_NODES + TB - 1) / TB;
    int edgeBlocks  = (N_EDGES + TB - 1) / TB;
    int edgeWBlocks = (N_EDGES * 32 + TB - 1) / TB;   // warp per edge

    // normalization coefficients
    k_deg_init<<<nodeBlocks, TB>>>();
    k_deg_acc<<<edgeBlocks, TB>>>(ei, ea);
    k_rsqrt<<<nodeBlocks, TB>>>();

    // layer 1: aggregate x per channel, then GEMM (+bias+relu) into concat H
    k_agg1_init<<<(N_NODES * 32 + TB - 1) / TB, TB>>>(x);
    k_scatter1<<<edgeWBlocks, TB>>>(x, ei, ea);
    L1Args a1;
    for (int c = 0; c < 4; c++) { a1.W[c] = W1a[c]; a1.b[c] = b1a[c]; }
    a1.A = pAgg1; a1.C = pH;
    dim3 grid1((N_NODES + 127) / 128, 1, 4);
    k_gemm1<<<grid1, 256>>>(a1);

    // layer 2: GEMM first (N=256 < K=512), then aggregate, then bias+relu
    dim3 grid2((N_NODES + 127) / 128, 2, 1);
    k_gemm<<<grid2, 256>>>(pH, 4 * DIM, W2, 2 * DIM, pZ2, 2 * DIM, N_NODES, 2 * DIM, 4 * DIM);
    k_agg2_init<<<(N_NODES * 64 + TB - 1) / TB, TB>>>();
    k_scatter2<<<edgeWBlocks, TB>>>(ei);
    k_bias_relu2<<<(N_NODES * 64 + TB - 1) / TB, TB>>>(b2);

    // layer 3: GEMM then aggregate (bias folded into pooling)
    dim3 grid3((N_NODES + 127) / 128, 1, 1);
    k_gemm<<<grid3, 256>>>(pH2, 2 * DIM, W3, DIM, pZ3, DIM, N_NODES, DIM, 2 * DIM);
    k_agg3_init<<<(N_NODES * 32 + TB - 1) / TB, TB>>>();
    k_scatter3<<<edgeWBlocks, TB>>>(ei);

    // pooling + MLP head
    k_pool_init<<<(NUM_GRAPHS * DIM + TB - 1) / TB, TB>>>();
    k_pool_acc<<<(N_NODES * 32 + TB - 1) / TB, TB>>>(batch, b3);
    k_mlp<<<NUM_GRAPHS, 256>>>(Wm1, bm1, Wm2, bm2, out);
}

// round 4
// speedup vs baseline: 1.4145x; 1.4145x over previous
#include <cuda_runtime.h>
#include <cuda_bf16.h>
#include <cstdint>
#include <cstddef>

#define N_NODES   50000
#define N_EDGES   600000
#define DIM       128
#define NUM_GRAPHS 64
#define TB 256
#define ASTRIDE 72   // smem row stride (bf16 elems): 64 data + 8 pad

// ==================== scratch ====================
__device__ float g_dis4[4][N_NODES];
__device__ float g_disu[N_NODES];
__device__ float g_agg1[4][N_NODES][DIM];
__device__ float g_H   [N_NODES][4 * DIM];
__device__ float g_Z2  [N_NODES][2 * DIM];
__device__ float g_agg2[N_NODES][2 * DIM];
__device__ float g_H2  [N_NODES][2 * DIM];
__device__ float g_Z3  [N_NODES][DIM];
__device__ float g_agg3[N_NODES][DIM];
__device__ float g_sums[NUM_GRAPHS][DIM];
__device__ float g_maxs[NUM_GRAPHS][DIM];
__device__ int   g_cnts[NUM_GRAPHS];
// transposed/split weights (B operand: [N,K] K-major bf16)
__device__ __nv_bfloat16 g_wt1hi[4 * 128 * 128];
__device__ __nv_bfloat16 g_wt1lo[4 * 128 * 128];
__device__ __nv_bfloat16 g_wt2hi[256 * 512];
__device__ __nv_bfloat16 g_wt2lo[256 * 512];
__device__ __nv_bfloat16 g_wt3hi[128 * 256];
__device__ __nv_bfloat16 g_wt3lo[128 * 256];
__device__ float g_b1cat[4 * DIM];

// ==================== helpers ====================
__device__ __forceinline__ uint32_t smem_u32(const void* p) {
    uint32_t a;
    asm("{ .reg .u64 t; cvta.to.shared.u64 t, %1; cvt.u32.u64 %0, t; }" : "=r"(a) : "l"(p));
    return a;
}
__device__ __forceinline__ void ldsm_x4(uint32_t addr, uint32_t& r0, uint32_t& r1,
                                        uint32_t& r2, uint32_t& r3) {
    asm volatile("ldmatrix.sync.aligned.m8n8.x4.shared.b16 {%0,%1,%2,%3}, [%4];"
                 : "=r"(r0), "=r"(r1), "=r"(r2), "=r"(r3) : "r"(addr));
}
__device__ __forceinline__ void mma16816(float* c, const uint32_t* a, uint32_t b0, uint32_t b1) {
    asm volatile(
        "mma.sync.aligned.m16n8k16.row.col.f32.bf16.bf16.f32 "
        "{%0,%1,%2,%3}, {%4,%5,%6,%7}, {%8,%9}, {%0,%1,%2,%3};"
        : "+f"(c[0]), "+f"(c[1]), "+f"(c[2]), "+f"(c[3])
        : "r"(a[0]), "r"(a[1]), "r"(a[2]), "r"(a[3]), "r"(b0), "r"(b1));
}
__device__ __forceinline__ uint32_t pack_bf2(float x, float y) {
    __nv_bfloat162 h = __floats2bfloat162_rn(x, y);
    return *reinterpret_cast<uint32_t*>(&h);
}
__device__ __forceinline__ void sts64(uint32_t a, uint32_t x, uint32_t y) {
    asm volatile("st.shared.v2.b32 [%0], {%1,%2};" :: "r"(a), "r"(x), "r"(y));
}
__device__ __forceinline__ void sts128(uint32_t a, uint4 v) {
    asm volatile("st.shared.v4.b32 [%0], {%1,%2,%3,%4};" :: "r"(a), "r"(v.x), "r"(v.y), "r"(v.z), "r"(v.w));
}
__device__ __forceinline__ void red4(float* p, float a, float b, float c, float d) {
    asm volatile("red.global.add.v4.f32 [%0], {%1,%2,%3,%4};"
                 :: "l"(p), "f"(a), "f"(b), "f"(c), "f"(d) : "memory");
}
__device__ __forceinline__ void atomicMaxF(float* addr, float v) {
    if (v >= 0.0f) atomicMax(reinterpret_cast<int*>(addr), __float_as_int(v));
    else           atomicMin(reinterpret_cast<unsigned int*>(addr), __float_as_uint(v));
}

// ==================== degree / normalization ====================
__global__ void k_deg_init() {
    int v = blockIdx.x * blockDim.x + threadIdx.x;
    if (v < N_NODES) {
        g_dis4[0][v] = 1.f; g_dis4[1][v] = 1.f; g_dis4[2][v] = 1.f; g_dis4[3][v] = 1.f;
        g_disu[v] = 1.f;
    }
}
__global__ void k_deg_acc(const int* __restrict__ ei, const float* __restrict__ ea) {
    int e = blockIdx.x * blockDim.x + threadIdx.x;
    if (e >= N_EDGES) return;
    int d = ei[N_EDGES + e];
    float4 w = *reinterpret_cast<const float4*>(ea + 4 * (size_t)e);
    atomicAdd(&g_dis4[0][d], w.x);
    atomicAdd(&g_dis4[1][d], w.y);
    atomicAdd(&g_dis4[2][d], w.z);
    atomicAdd(&g_dis4[3][d], w.w);
    atomicAdd(&g_disu[d], 1.0f);
}
__global__ void k_rsqrt() {
    int v = blockIdx.x * blockDim.x + threadIdx.x;
    if (v < N_NODES) {
        #pragma unroll
        for (int c = 0; c < 4; c++) g_dis4[c][v] = rsqrtf(g_dis4[c][v]);
        g_disu[v] = rsqrtf(g_disu[v]);
    }
}

// ==================== weight transpose + hi/lo split ====================
__global__ void k_wsplit(const float* __restrict__ W, __nv_bfloat16* __restrict__ hi,
                         __nv_bfloat16* __restrict__ lo, int K, int N) {
    int i = blockIdx.x * blockDim.x + threadIdx.x;
    if (i >= K * N) return;
    int k = i / N, n = i % N;
    float w = W[i];
    __nv_bfloat16 h = __float2bfloat16_rn(w);
    float l = w - __bfloat162float(h);
    hi[(size_t)n * K + k] = h;
    lo[(size_t)n * K + k] = __float2bfloat16_rn(l);
}
__global__ void k_pack_bias(const float* a, const float* b, const float* c, const float* d) {
    int i = threadIdx.x;  // 128
    g_b1cat[i] = a[i]; g_b1cat[128 + i] = b[i];
    g_b1cat[256 + i] = c[i]; g_b1cat[384 + i] = d[i];
}

// ==================== layer 1 aggregation ====================
__global__ void k_agg1_init(const float* __restrict__ x) {
    int idx = blockIdx.x * blockDim.x + threadIdx.x;
    if (idx >= N_NODES * 32) return;
    int v = idx >> 5, q = idx & 31;
    float4 xv = *reinterpret_cast<const float4*>(x + (size_t)v * DIM + q * 4);
    #pragma unroll
    for (int c = 0; c < 4; c++) {
        float s = g_dis4[c][v]; s = s * s;
        float4 o = make_float4(xv.x * s, xv.y * s, xv.z * s, xv.w * s);
        *reinterpret_cast<float4*>(&g_agg1[c][v][q * 4]) = o;
    }
}
__global__ void k_scatter1(const float* __restrict__ x, const int* __restrict__ ei,
                           const float* __restrict__ ea) {
    int t = blockIdx.x * blockDim.x + threadIdx.x;
    int e = t >> 5, lane = t & 31;
    if (e >= N_EDGES) return;
    int s = __ldg(ei + e), d = __ldg(ei + N_EDGES + e);
    float4 w = *reinterpret_cast<const float4*>(ea + 4 * (size_t)e);
    float c0 = g_dis4[0][s] * w.x * g_dis4[0][d];
    float c1 = g_dis4[1][s] * w.y * g_dis4[1][d];
    float c2 = g_dis4[2][s] * w.z * g_dis4[2][d];
    float c3 = g_dis4[3][s] * w.w * g_dis4[3][d];
    float4 xv = *reinterpret_cast<const float4*>(x + (size_t)s * DIM + lane * 4);
    red4(&g_agg1[0][d][lane * 4], xv.x * c0, xv.y * c0, xv.z * c0, xv.w * c0);
    red4(&g_agg1[1][d][lane * 4], xv.x * c1, xv.y * c1, xv.z * c1, xv.w * c1);
    red4(&g_agg1[2][d][lane * 4], xv.x * c2, xv.y * c2, xv.z * c2, xv.w * c2);
    red4(&g_agg1[3][d][lane * 4], xv.x * c3, xv.y * c3, xv.z * c3, xv.w * c3);
}

// ==================== mma.sync GEMM (bf16 3-term split, fp32 acc) ====================
// C[M, n0:n0+128] = A[M,K] @ Bt where B stored [N,K] K-major bf16 hi/lo.
struct GemmArgs {
    const float* A; size_t aZ; int lda;
    const __nv_bfloat16* Bhi; const __nv_bfloat16* Blo; size_t bZ;
    float* C; size_t cZ; int ldc;
    const float* bias; size_t biasZ;
    int M, K, relu, hasBias;
};

__global__ void __launch_bounds__(256, 2) k_mma_gemm(GemmArgs g) {
    extern __shared__ __nv_bfloat16 sm[];
    __nv_bfloat16* sAhi = sm;
    __nv_bfloat16* sAlo = sAhi + 128 * ASTRIDE;
    __nv_bfloat16* sBhi = sAlo + 128 * ASTRIDE;
    __nv_bfloat16* sBlo = sBhi + 128 * ASTRIDE;
    uint32_t uAhi = smem_u32(sAhi), uAlo = smem_u32(sAlo);
    uint32_t uBhi = smem_u32(sBhi), uBlo = smem_u32(sBlo);

    int t = threadIdx.x, lane = t & 31, wid = t >> 5;
    int z = blockIdx.z;
    const float* A = g.A + g.aZ * z;
    const __nv_bfloat16* Bh = g.Bhi + g.bZ * z;
    const __nv_bfloat16* Bl = g.Blo + g.bZ * z;
    float* C = g.C + g.cZ * z;
    const float* bias = g.bias + g.biasZ * z;
    int m0 = blockIdx.x * 128, n0 = blockIdx.y * 128;
    int warpM = wid & 3, warpN = wid >> 2;      // 4 x 2 warp grid
    int m0w = warpM * 32, n0w = warpN * 64;     // warp tile 32 x 64

    float acc[2][8][4];
    #pragma unroll
    for (int i = 0; i < 2; i++)
        #pragma unroll
        for (int j = 0; j < 8; j++)
            #pragma unroll
            for (int q = 0; q < 4; q++) acc[i][j][q] = 0.0f;

    // ldmatrix per-lane base coordinates (element units within tile)
    int a_row = (lane & 7) + ((lane >> 3) & 1) * 8;  // + mt*16
    int a_col = (lane >> 4) * 8;                     // + ks*16
    int b_row = (lane & 7) + (lane >> 4) * 8;        // + ntp*16  (n index)
    int b_col = ((lane >> 3) & 1) * 8;               // + ks*16   (k index)

    int nchunks = g.K >> 6;
    for (int ch = 0; ch < nchunks; ch++) {
        int k0c = ch << 6;
        // --- A tile: 128x64 fp32 -> hi/lo bf16 ---
        #pragma unroll
        for (int l = 0; l < 8; l++) {
            int f = l * 256 + t;              // 2048 float4s
            int row = f >> 4, c4 = f & 15;
            int gm = m0 + row;
            float4 v = make_float4(0.f, 0.f, 0.f, 0.f);
            if (gm < g.M)
                v = *reinterpret_cast<const float4*>(A + (size_t)gm * g.lda + k0c + c4 * 4);
            __nv_bfloat16 hx = __float2bfloat16_rn(v.x), hy = __float2bfloat16_rn(v.y);
            __nv_bfloat16 hz = __float2bfloat16_rn(v.z), hw = __float2bfloat16_rn(v.w);
            uint32_t h01, h23;
            { __nv_bfloat162 p; p.x = hx; p.y = hy; h01 = *reinterpret_cast<uint32_t*>(&p); }
            { __nv_bfloat162 p; p.x = hz; p.y = hw; h23 = *reinterpret_cast<uint32_t*>(&p); }
            uint32_t l01 = pack_bf2(v.x - __bfloat162float(hx), v.y - __bfloat162float(hy));
            uint32_t l23 = pack_bf2(v.z - __bfloat162float(hz), v.w - __bfloat162float(hw));
            uint32_t off = (uint32_t)(row * ASTRIDE + c4 * 4) * 2;
            sts64(uAhi + off, h01, h23);
            sts64(uAlo + off, l01, l23);
        }
        // --- B tiles: 128x64 bf16 (pre-split) ---
        #pragma unroll
        for (int l = 0; l < 4; l++) {
            int f = l * 256 + t;              // 1024 uint4s
            int row = f >> 3, u = f & 7;
            size_t off = (size_t)(n0 + row) * g.K + k0c + u * 8;
            uint4 vh = *reinterpret_cast<const uint4*>(Bh + off);
            uint4 vl = *reinterpret_cast<const uint4*>(Bl + off);
            uint32_t so = (uint32_t)(row * ASTRIDE + u * 8) * 2;
            sts128(uBhi + so, vh);
            sts128(uBlo + so, vl);
        }
        __syncthreads();

        #pragma unroll
        for (int ks = 0; ks < 4; ks++) {
            int k0 = ks * 16;
            uint32_t ah[2][4], al[2][4];
            #pragma unroll
            for (int mt = 0; mt < 2; mt++) {
                uint32_t off = (uint32_t)((m0w + mt * 16 + a_row) * ASTRIDE + k0 + a_col) * 2;
                ldsm_x4(uAhi + off, ah[mt][0], ah[mt][1], ah[mt][2], ah[mt][3]);
                ldsm_x4(uAlo + off, al[mt][0], al[mt][1], al[mt][2], al[mt][3]);
            }
            #pragma unroll
            for (int ntp = 0; ntp < 4; ntp++) {
                uint32_t off = (uint32_t)((n0w + ntp * 16 + b_row) * ASTRIDE + k0 + b_col) * 2;
                uint32_t bh[4], bl[4];
                ldsm_x4(uBhi + off, bh[0], bh[1], bh[2], bh[3]);
                ldsm_x4(uBlo + off, bl[0], bl[1], bl[2], bl[3]);
                #pragma unroll
                for (int mt = 0; mt < 2; mt++) {
                    mma16816(acc[mt][ntp * 2],     ah[mt], bh[0], bh[1]);
                    mma16816(acc[mt][ntp * 2 + 1], ah[mt], bh[2], bh[3]);
                    mma16816(acc[mt][ntp * 2],     ah[mt], bl[0], bl[1]);
                    mma16816(acc[mt][ntp * 2 + 1], ah[mt], bl[2], bl[3]);
                    mma16816(acc[mt][ntp * 2],     al[mt], bh[0], bh[1]);
                    mma16816(acc[mt][ntp * 2 + 1], al[mt], bh[2], bh[3]);
                }
            }
        }
        __syncthreads();
    }

    // --- epilogue ---
    int gq = lane >> 2, tq = lane & 3;
    #pragma unroll
    for (int mt = 0; mt < 2; mt++) {
        #pragma unroll
        for (int half = 0; half < 2; half++) {
            int gm = m0 + m0w + mt * 16 + gq + half * 8;
            if (gm >= g.M) continue;
            float* cp = C + (size_t)gm * g.ldc;
            #pragma unroll
            for (int nt = 0; nt < 8; nt++) {
                int col = n0w + nt * 8 + tq * 2;
                float vx = acc[mt][nt][half * 2];
                float vy = acc[mt][nt][half * 2 + 1];
                if (g.hasBias) {
                    vx += __ldg(bias + n0 + col);
                    vy += __ldg(bias + n0 + col + 1);
                }
                if (g.relu) { vx = fmaxf(vx, 0.f); vy = fmaxf(vy, 0.f); }
                *reinterpret_cast<float2*>(cp + n0 + col) = make_float2(vx, vy);
            }
        }
    }
}

// ==================== layer 2 aggregation (256-dim) ====================
__global__ void k_agg2_init() {
    int idx = blockIdx.x * blockDim.x + threadIdx.x;
    if (idx >= N_NODES * 64) return;
    int v = idx >> 6, q = idx & 63;
    float s = g_disu[v]; s = s * s;
    float4 zv = *reinterpret_cast<const float4*>(&g_Z2[v][q * 4]);
    float4 o = make_float4(zv.x * s, zv.y * s, zv.z * s, zv.w * s);
    *reinterpret_cast<float4*>(&g_agg2[v][q * 4]) = o;
}
__global__ void k_scatter2(const int* __restrict__ ei) {
    int t = blockIdx.x * blockDim.x + threadIdx.x;
    int e = t >> 5, lane = t & 31;
    if (e >= N_EDGES) return;
    int s = __ldg(ei + e), d = __ldg(ei + N_EDGES + e);
    float coef = g_disu[s] * g_disu[d];
    #pragma unroll
    for (int h = 0; h < 2; h++) {
        int q = lane + h * 32;
        float4 zv = *reinterpret_cast<const float4*>(&g_Z2[s][q * 4]);
        red4(&g_agg2[d][q * 4], zv.x * coef, zv.y * coef, zv.z * coef, zv.w * coef);
    }
}
__global__ void k_bias_relu2(const float* __restrict__ b2) {
    int idx = blockIdx.x * blockDim.x + threadIdx.x;
    if (idx >= N_NODES * 64) return;
    int v = idx >> 6, q = idx & 63;
    float4 a = *reinterpret_cast<const float4*>(&g_agg2[v][q * 4]);
    float4 b = *reinterpret_cast<const float4*>(&b2[q * 4]);
    float4 o = make_float4(fmaxf(a.x + b.x, 0.f), fmaxf(a.y + b.y, 0.f),
                           fmaxf(a.z + b.z, 0.f), fmaxf(a.w + b.w, 0.f));
    *reinterpret_cast<float4*>(&g_H2[v][q * 4]) = o;
}

// ==================== layer 3 aggregation (128-dim) ====================
__global__ void k_agg3_init() {
    int idx = blockIdx.x * blockDim.x + threadIdx.x;
    if (idx >= N_NODES * 32) return;
    int v = idx >> 5, q = idx & 31;
    float s = g_disu[v]; s = s * s;
    float4 zv = *reinterpret_cast<const float4*>(&g_Z3[v][q * 4]);
    float4 o = make_float4(zv.x * s, zv.y * s, zv.z * s, zv.w * s);
    *reinterpret_cast<float4*>(&g_agg3[v][q * 4]) = o;
}
__global__ void k_scatter3(const int* __restrict__ ei) {
    int t = blockIdx.x * blockDim.x + threadIdx.x;
    int e = t >> 5, lane = t & 31;
    if (e >= N_EDGES) return;
    int s = __ldg(ei + e), d = __ldg(ei + N_EDGES + e);
    float coef = g_disu[s] * g_disu[d];
    float4 zv = *reinterpret_cast<const float4*>(&g_Z3[s][lane * 4]);
    red4(&g_agg3[d][lane * 4], zv.x * coef, zv.y * coef, zv.z * coef, zv.w * coef);
}

// ==================== pooling + MLP ====================
__global__ void k_pool_init() {
    int idx = blockIdx.x * blockDim.x + threadIdx.x;
    if (idx < NUM_GRAPHS * DIM) {
        (&g_sums[0][0])[idx] = 0.0f;
        (&g_maxs[0][0])[idx] = __int_as_float(0xff800000);
        if (idx < NUM_GRAPHS) g_cnts[idx] = 0;
    }
}
__global__ void k_pool_acc(const int* __restrict__ batch, const float* __restrict__ b3) {
    int t = blockIdx.x * blockDim.x + threadIdx.x;
    int v = t >> 5, lane = t & 31;
    if (v >= N_NODES) return;
    int g = __ldg(batch + v);
    if (lane == 0) atomicAdd(&g_cnts[g], 1);
    float4 a = *reinterpret_cast<const float4*>(&g_agg3[v][lane * 4]);
    float4 b = *reinterpret_cast<const float4*>(&b3[lane * 4]);
    a.x += b.x; a.y += b.y; a.z += b.z; a.w += b.w;
    red4(&g_sums[g][lane * 4], a.x, a.y, a.z, a.w);
    atomicMaxF(&g_maxs[g][lane * 4 + 0], a.x);
    atomicMaxF(&g_maxs[g][lane * 4 + 1], a.y);
    atomicMaxF(&g_maxs[g][lane * 4 + 2], a.z);
    atomicMaxF(&g_maxs[g][lane * 4 + 3], a.w);
}
__global__ void k_mlp(const float* __restrict__ Wm1, const float* __restrict__ bm1,
                      const float* __restrict__ Wm2, const float* __restrict__ bm2,
                      float* __restrict__ out) {
    int g = blockIdx.x;
    int t = threadIdx.x;
    __shared__ float sg[2 * DIM];
    __shared__ float sh[8];
    int cnt = g_cnts[g];
    float val;
    if (t < DIM) {
        val = g_sums[g][t] / fmaxf((float)cnt, 1.0f);
    } else {
        float m = g_maxs[g][t - DIM];
        val = (cnt > 0) ? m : 0.0f;
    }
    sg[t] = val;
    __syncthreads();
    if (t < 8) {
        float h = bm1[t];
        #pragma unroll 8
        for (int j = 0; j < 2 * DIM; j++) h += sg[j] * Wm1[j * 8 + t];
        sh[t] = fmaxf(h, 0.0f);
    }
    __syncthreads();
    if (t < 2) {
        float o = bm2[t];
        #pragma unroll
        for (int k = 0; k < 8; k++) o += sh[k] * Wm2[k * 2 + t];
        out[g * 2 + t] = o;
    }
}

// ==================== launch ====================
extern "C" void kernel_launch(void* const* d_in, const int* in_sizes, int n_in,
                              void* d_out, int out_size) {
    const float* x     = (const float*)d_in[0];
    const int*   ei    = (const int*)d_in[1];
    const float* ea    = (const float*)d_in[2];
    const int*   batch = (const int*)d_in[3];
    const float* W1a[4] = {(const float*)d_in[4], (const float*)d_in[6],
                           (const float*)d_in[8], (const float*)d_in[10]};
    const float* b1a[4] = {(const float*)d_in[5], (const float*)d_in[7],
                           (const float*)d_in[9], (const float*)d_in[11]};
    const float* W2  = (const float*)d_in[12];
    const float* b2  = (const float*)d_in[13];
    const float* W3  = (const float*)d_in[14];
    const float* b3  = (const float*)d_in[15];
    const float* Wm1 = (const float*)d_in[16];
    const float* bm1 = (const float*)d_in[17];
    const float* Wm2 = (const float*)d_in[18];
    const float* bm2 = (const float*)d_in[19];
    float* out = (float*)d_out;

    float *pAgg1, *pH, *pZ2, *pH2, *pZ3, *pB1;
    __nv_bfloat16 *pW1h, *pW1l, *pW2h, *pW2l, *pW3h, *pW3l;
    cudaGetSymbolAddress((void**)&pAgg1, g_agg1);
    cudaGetSymbolAddress((void**)&pH,    g_H);
    cudaGetSymbolAddress((void**)&pZ2,   g_Z2);
    cudaGetSymbolAddress((void**)&pH2,   g_H2);
    cudaGetSymbolAddress((void**)&pZ3,   g_Z3);
    cudaGetSymbolAddress((void**)&pB1,   g_b1cat);
    cudaGetSymbolAddress((void**)&pW1h,  g_wt1hi);
    cudaGetSymbolAddress((void**)&pW1l,  g_wt1lo);
    cudaGetSymbolAddress((void**)&pW2h,  g_wt2hi);
    cudaGetSymbolAddress((void**)&pW2l,  g_wt2lo);
    cudaGetSymbolAddress((void**)&pW3h,  g_wt3hi);
    cudaGetSymbolAddress((void**)&pW3l,  g_wt3lo);

    static const int SMEM_GEMM = 4 * 128 * ASTRIDE * 2;  // 73728 B
    cudaFuncSetAttribute(k_mma_gemm, cudaFuncAttributeMaxDynamicSharedMemorySize, SMEM_GEMM);

    int nodeBlocks  = (N_NODES + TB - 1) / TB;
    int edgeBlocks  = (N_EDGES + TB - 1) / TB;
    int edgeWBlocks = (N_EDGES * 32 + TB - 1) / TB;
    int mTiles = (N_NODES + 127) / 128;

    // normalization
    k_deg_init<<<nodeBlocks, TB>>>();
    k_deg_acc<<<edgeBlocks, TB>>>(ei, ea);
    k_rsqrt<<<nodeBlocks, TB>>>();

    // weight prep (tiny)
    for (int c = 0; c < 4; c++)
        k_wsplit<<<(128 * 128 + TB - 1) / TB, TB>>>(W1a[c], pW1h + c * 16384, pW1l + c * 16384, 128, 128);
    k_wsplit<<<(512 * 256 + TB - 1) / TB, TB>>>(W2, pW2h, pW2l, 512, 256);
    k_wsplit<<<(256 * 128 + TB - 1) / TB, TB>>>(W3, pW3h, pW3l, 256, 128);
    k_pack_bias<<<1, 128>>>(b1a[0], b1a[1], b1a[2], b1a[3]);

    // layer 1: aggregate x per channel, then 4 batched GEMMs (+bias+relu) into concat H
    k_agg1_init<<<(N_NODES * 32 + TB - 1) / TB, TB>>>(x);
    k_scatter1<<<edgeWBlocks, TB>>>(x, ei, ea);
    {
        GemmArgs a;
        a.A = pAgg1; a.aZ = (size_t)N_NODES * DIM; a.lda = DIM;
        a.Bhi = pW1h; a.Blo = pW1l; a.bZ = 16384;
        a.C = pH; a.cZ = DIM; a.ldc = 4 * DIM;
        a.bias = pB1; a.biasZ = DIM;
        a.M = N_NODES; a.K = DIM; a.relu = 1; a.hasBias = 1;
        k_mma_gemm<<<dim3(mTiles, 1, 4), 256, SMEM_GEMM>>>(a);
    }

    // layer 2: GEMM first, then aggregate, then bias+relu
    {
        GemmArgs a;
        a.A = pH; a.aZ = 0; a.lda = 4 * DIM;
        a.Bhi = pW2h; a.Blo = pW2l; a.bZ = 0;
        a.C = pZ2; a.cZ = 0; a.ldc = 2 * DIM;
        a.bias = pB1; a.biasZ = 0;
        a.M = N_NODES; a.K = 4 * DIM; a.relu = 0; a.hasBias = 0;
        k_mma_gemm<<<dim3(mTiles, 2, 1), 256, SMEM_GEMM>>>(a);
    }
    k_agg2_init<<<(N_NODES * 64 + TB - 1) / TB, TB>>>();
    k_scatter2<<<edgeWBlocks, TB>>>(ei);
    k_bias_relu2<<<(N_NODES * 64 + TB - 1) / TB, TB>>>(b2);

    // layer 3
    {
        GemmArgs a;
        a.A = pH2; a.aZ = 0; a.lda = 2 * DIM;
        a.Bhi = pW3h; a.Blo = pW3l; a.bZ = 0;
        a.C = pZ3; a.cZ = 0; a.ldc = DIM;
        a.bias = pB1; a.biasZ = 0;
        a.M = N_NODES; a.K = 2 * DIM; a.relu = 0; a.hasBias = 0;
        k_mma_gemm<<<dim3(mTiles, 1, 1), 256, SMEM_GEMM>>>(a);
    }
    k_agg3_init<<<(N_NODES * 32 + TB - 1) / TB, TB>>>();
    k_scatter3<<<edgeWBlocks, TB>>>(ei);

    // pooling + MLP
    k_pool_init<<<(NUM_GRAPHS * DIM + TB - 1) / TB, TB>>>();
    k_pool_acc<<<(N_NODES * 32 + TB - 1) / TB, TB>>>(batch, b3);
    k_mlp<<<NUM_GRAPHS, 256>>>(Wm1, bm1, Wm2, bm2, out);
}